// round 5
// baseline (speedup 1.0000x reference)
#include <cuda_runtime.h>

// ElevationLoss: tversky(logits, gt) * elevation(softmax, heights, gt)
// B=8, C=2, H=W=512, gt in {0,1}. Single fused kernel, last-block finalize.
// Register-streamed 3x6 window: one row live at a time, int stencil accums.

#define IMG_H 512
#define IMG_W 512
#define HW (IMG_H * IMG_W)        // 262144
#define NBATCH 8
#define NPIX (NBATCH * HW)        // 2097152
#define NGROUP (NPIX / 4)         // 524288 groups of 4 consecutive x-pixels
#define NT 256
#define NB (NGROUP / NT)          // 2048 blocks
#define NACC 5

// Per-block partials: [Σp1, inter1, count1, comb_sum, ud_sum]
__device__ float g_part[NB * 8];
__device__ unsigned g_count = 0;   // reset by last block each launch

__device__ __forceinline__ float block_reduce(float v, float* sh) {
    #pragma unroll
    for (int o = 16; o > 0; o >>= 1) v += __shfl_down_sync(0xffffffffu, v, o);
    int lane = threadIdx.x & 31;
    int w = threadIdx.x >> 5;
    __syncthreads();                 // protect sh reuse across calls
    if (lane == 0) sh[w] = v;
    __syncthreads();
    if (w == 0) {
        v = (lane < NT / 32) ? sh[lane] : 0.0f;
        #pragma unroll
        for (int o = 4; o > 0; o >>= 1) v += __shfl_down_sync(0xffffffffu, v, o);
    }
    return v;   // valid in thread 0
}

__global__ __launch_bounds__(NT) void elev_fused(
    const float* __restrict__ pred,   // (B,2,H,W)
    const float* __restrict__ hgt,    // (B,1,H,W)
    const int*   __restrict__ gt,     // (B,1,H,W)
    float* __restrict__ out)
{
    float s_p1 = 0.f, s_i1 = 0.f, s_ud = 0.f;
    int   c1i = 0, cbi = 0;

    {
        int g  = blockIdx.x * NT + threadIdx.x;   // exactly NGROUP threads
        int b  = g >> 16;          // 65536 groups per image
        int r4 = g & 65535;
        int y  = r4 >> 7;          // 128 groups per row
        int xg = r4 & 127;
        int x0 = xg << 2;

        const float* pb = pred + ((size_t)b * 2) * HW;
        const float* hb = hgt + (size_t)b * HW;
        const int*   gb = gt  + (size_t)b * HW;

        float hc[4];          // center heights
        float u[4];           // unified pred per pixel
        int   ddi[4] = {0, 0, 0, 0};

        // Row loader into (nsi = 2g-1, nsg = (float)nsi, hw = -nsg*h).
        // pass iff sg*(h-hc) <= 0 with sg = -nsg:
        //   m = fma(nsg, hc, hw) <= 0
        // Zero padding (reference unfold): OOB -> g=0, h=0.
        int   nsi[6];
        float nsg[6], hw[6];

        auto load_row = [&](int ry) {
            int   gg[6];
            float hh[6];
            if ((unsigned)ry < (unsigned)IMG_H) {
                int4   gv = ((const int4*)  gb)[(ry << 7) + xg];
                float4 hv = ((const float4*)hb)[(ry << 7) + xg];
                gg[1] = gv.x; gg[2] = gv.y; gg[3] = gv.z; gg[4] = gv.w;
                hh[1] = hv.x; hh[2] = hv.y; hh[3] = hv.z; hh[4] = hv.w;
                gg[0] = (x0 > 0)         ? gb[(ry << 9) + x0 - 1] : 0;
                hh[0] = (x0 > 0)         ? hb[(ry << 9) + x0 - 1] : 0.f;
                gg[5] = (x0 + 4 < IMG_W) ? gb[(ry << 9) + x0 + 4] : 0;
                hh[5] = (x0 + 4 < IMG_W) ? hb[(ry << 9) + x0 + 4] : 0.f;
            } else {
                #pragma unroll
                for (int j = 0; j < 6; j++) { gg[j] = 0; hh[j] = 0.f; }
            }
            #pragma unroll
            for (int j = 0; j < 6; j++) {
                nsi[j] = 2 * gg[j] - 1;
                nsg[j] = (float)nsi[j];
                hw[j]  = -nsg[j] * hh[j];
            }
        };

        auto stencil_row = [&]() {
            #pragma unroll
            for (int px = 0; px < 4; px++) {
                #pragma unroll
                for (int dx = 0; dx < 3; dx++) {
                    int j = px + dx;
                    float m = fmaf(nsg[j], hc[px], hw[j]);
                    bool pr = (m <= 0.f);
                    if (pr) cbi++;
                    if (pr) ddi[px] -= nsi[j];
                }
            }
        };

        // ---- center row first (provides hc + tversky center class) ----
        load_row(y);
        {
            #pragma unroll
            for (int px = 0; px < 4; px++) hc[px] = -nsg[px + 1] * hw[px + 1];
            // hw = sg*h, so h = sg*hw = (-nsg)*hw -> hc = -nsg*hw. Exact (sg=±1).

            // tversky center class: flood iff nsi==1
            #pragma unroll
            for (int px = 0; px < 4; px++) c1i += (nsi[px + 1] + 1) >> 1;
        }

        // ---- logits: softmax + unified pred + tversky prob partials ----
        {
            float4 l0v = ((const float4*)pb)[(y << 7) + xg];
            float4 l1v = ((const float4*)pb)[(HW >> 2) + (y << 7) + xg];
            float t[4] = {l1v.x - l0v.x, l1v.y - l0v.y,
                          l1v.z - l0v.z, l1v.w - l0v.w};
            #pragma unroll
            for (int px = 0; px < 4; px++) {
                float p1 = 1.0f / (1.0f + __expf(-t[px]));
                s_p1 += p1;
                if (nsi[px + 1] > 0) s_i1 += p1;   // center flood
                u[px] = (t[px] > 0.f) ? p1 : p1 - 1.f;
            }
        }

        stencil_row();          // center row stencil (row regs still live)
        load_row(y - 1);
        stencil_row();
        load_row(y + 1);
        stencil_row();

        #pragma unroll
        for (int px = 0; px < 4; px++)
            s_ud = fmaf(u[px], (float)ddi[px], s_ud);
    }

    // ---- per-block reduction ----
    __shared__ float sh[NT / 32];
    {
        float acc[NACC] = {s_p1, s_i1, (float)c1i, (float)cbi, s_ud};
        #pragma unroll
        for (int k = 0; k < NACC; k++) {
            float r = block_reduce(acc[k], sh);
            if (threadIdx.x == 0) g_part[blockIdx.x * 8 + k] = r;
        }
    }

    // ---- last-block finalize ----
    __shared__ bool is_last;
    if (threadIdx.x == 0) {
        __threadfence();                     // publish this block's partials
        unsigned c = atomicAdd(&g_count, 1u);
        is_last = (c == (unsigned)(NB - 1));
    }
    __syncthreads();
    if (!is_last) return;
    __threadfence();                         // acquire all blocks' partials

    float acc[NACC];
    #pragma unroll
    for (int k = 0; k < NACC; k++) acc[k] = 0.0f;
    for (int i = threadIdx.x; i < NB; i += NT) {
        #pragma unroll
        for (int k = 0; k < NACC; k++) acc[k] += g_part[i * 8 + k];
    }
    float tot[NACC];
    #pragma unroll
    for (int k = 0; k < NACC; k++) tot[k] = block_reduce(acc[k], sh);

    if (threadIdx.x == 0) {
        const float ALPHA = 0.3f, BETA = 0.7f, GAMMA = 1.33f, EPS = 1e-7f;
        float p1s  = tot[0];
        float i1   = tot[1];
        float c1   = tot[2];
        float csum = tot[3];
        float uds  = tot[4];

        float p0s = (float)NPIX - p1s;
        float c0  = (float)NPIX - c1;
        float i0  = (float)NPIX - c1 - p1s + i1;   // sum((1-cf)*(1-p1))

        float fp0 = p0s - i0;
        float fn0 = c0 - i0;
        float d0  = fmaxf(i0 + ALPHA * fp0 + BETA * fn0 + EPS, EPS);
        float loss0 = powf(1.0f - i0 / d0, GAMMA) * (c0 > 0.0f ? 1.0f : 0.0f);

        float fp1 = p1s - i1;
        float fn1 = c1 - i1;
        float d1  = fmaxf(i1 + ALPHA * fp1 + BETA * fn1 + EPS, EPS);
        float loss1 = powf(1.0f - i1 / d1, GAMMA) * (c1 > 0.0f ? 1.0f : 0.0f);

        float tversky = 0.5f * (loss0 + loss1);
        float elev    = (csum + uds) / fmaxf(csum, 1.0f);

        out[0] = tversky * elev;
        g_count = 0;   // reset for next graph replay
    }
}

extern "C" void kernel_launch(void* const* d_in, const int* in_sizes, int n_in,
                              void* d_out, int out_size)
{
    const float* pred = (const float*)d_in[0];   // (8,2,512,512) f32
    const float* hgt  = (const float*)d_in[1];   // (8,1,512,512) f32
    const int*   gt   = (const int*)  d_in[2];   // (8,1,512,512) i32
    float* out = (float*)d_out;

    elev_fused<<<NB, NT>>>(pred, hgt, gt, out);
}

// round 6
// speedup vs baseline: 1.0445x; 1.0445x over previous
#include <cuda_runtime.h>

// ElevationLoss: tversky(logits, gt) * elevation(softmax, heights, gt)
// B=8, C=2, H=W=512, gt in {0,1}. Single fused kernel, last-block finalize.
// Each thread: 4-wide x 2-tall pixel tile; 6-wide x 4-row window.

#define IMG_H 512
#define IMG_W 512
#define HW (IMG_H * IMG_W)        // 262144
#define NBATCH 8
#define NPIX (NBATCH * HW)        // 2097152
#define NTHREADS (NPIX / 8)       // 262144 (8 px per thread)
#define NT 128
#define NB (NTHREADS / NT)        // 2048 blocks
#define NACC 5

// Per-block partials: [Σp1, inter1, count1, comb_sum, ud_sum]
__device__ float g_part[NB * 8];
__device__ unsigned g_count = 0;   // reset by last block each launch

__device__ __forceinline__ float block_reduce(float v, float* sh) {
    #pragma unroll
    for (int o = 16; o > 0; o >>= 1) v += __shfl_down_sync(0xffffffffu, v, o);
    int lane = threadIdx.x & 31;
    int w = threadIdx.x >> 5;
    __syncthreads();                 // protect sh reuse across calls
    if (lane == 0) sh[w] = v;
    __syncthreads();
    if (w == 0) {
        v = (lane < NT / 32) ? sh[lane] : 0.0f;
        #pragma unroll
        for (int o = NT / 64; o > 0; o >>= 1)
            v += __shfl_down_sync(0xffffffffu, v, o);
    }
    return v;   // valid in thread 0
}

__global__ __launch_bounds__(NT) void elev_fused(
    const float* __restrict__ pred,   // (B,2,H,W)
    const float* __restrict__ hgt,    // (B,1,H,W)
    const int*   __restrict__ gt,     // (B,1,H,W)
    float* __restrict__ out)
{
    float s_p1 = 0.f, s_i1 = 0.f, s_ud = 0.f;
    int cbi = 0;
    unsigned flm = 0;                 // center-flood bitmask (8 px)

    {
        int g  = blockIdx.x * NT + threadIdx.x;   // exactly NTHREADS threads
        int b  = g >> 15;          // 32768 tiles per image
        int r  = g & 32767;
        int ty = r >> 7;           // 256 tile-rows
        int xg = r & 127;          // 128 tiles per row
        int x0 = xg << 2;
        int y0 = ty << 1;

        const float* pb = pred + ((size_t)b * 2) * HW;
        const float* hb = hgt + (size_t)b * HW;
        const int*   gb = gt  + (size_t)b * HW;

        // Logits first: overlap their latency with the window loads.
        float4 l0a = ((const float4*)pb)[( y0      << 7) + xg];
        float4 l1a = ((const float4*)pb)[(HW >> 2) + (( y0      ) << 7) + xg];
        float4 l0b = ((const float4*)pb)[((y0 + 1) << 7) + xg];
        float4 l1b = ((const float4*)pb)[(HW >> 2) + ((y0 + 1) << 7) + xg];

        float hc[8];                  // center heights (px 0..3 row0, 4..7 row1)
        float u[8];                   // unified pred
        int   acc[8] = {0,0,0,0,0,0,0,0};   // hi16: cb, lo16: cb+dd

        // Row buffers: sg = 2g-1 (so actual gt_sign = -sg),
        // hw = -sg*h, enc = (1<<16) + (1 - sg_int_here)... see below.
        int   encA[6], encB[6];
        float sgA[6], sgB[6], hwA[6], hwB[6];

        // load a 6-wide window row; crow>=0 captures centers into hc/flm.
        auto load6 = [&](int ry, int crow, int* enc, float* sgv, float* hwv) {
            int   gg[6];
            float hh[6];
            if ((unsigned)ry < (unsigned)IMG_H) {
                int4   gv = ((const int4*)  gb)[(ry << 7) + xg];
                float4 hv = ((const float4*)hb)[(ry << 7) + xg];
                gg[1] = gv.x; gg[2] = gv.y; gg[3] = gv.z; gg[4] = gv.w;
                hh[1] = hv.x; hh[2] = hv.y; hh[3] = hv.z; hh[4] = hv.w;
                gg[0] = (x0 > 0)         ? gb[(ry << 9) + x0 - 1] : 0;
                hh[0] = (x0 > 0)         ? hb[(ry << 9) + x0 - 1] : 0.f;
                gg[5] = (x0 + 4 < IMG_W) ? gb[(ry << 9) + x0 + 4] : 0;
                hh[5] = (x0 + 4 < IMG_W) ? hb[(ry << 9) + x0 + 4] : 0.f;
            } else {
                #pragma unroll
                for (int j = 0; j < 6; j++) { gg[j] = 0; hh[j] = 0.f; }
            }
            if (crow >= 0) {
                #pragma unroll
                for (int px = 0; px < 4; px++) {
                    hc[crow + px] = hh[px + 1];
                    flm |= (unsigned)gg[px + 1] << (crow + px);
                }
            }
            #pragma unroll
            for (int j = 0; j < 6; j++) {
                int nsi = 2 * gg[j] - 1;          // -gt_sign
                enc[j]  = 65537 - nsi;            // (1<<16) + (1 + gt_sign... )
                sgv[j]  = (float)nsi;
                hwv[j]  = -sgv[j] * hh[j];
            }
        };

        // pair test: m = sgv*(hc-h) = gt_sign*(h-hc); pass iff m <= 0.
        // Pass contributes enc: hi16 += 1 (cb), lo16 += 1+sign (cb+dd).
        auto sten = [&](int pr, const int* enc, const float* sgv, const float* hwv) {
            #pragma unroll
            for (int px = 0; px < 4; px++) {
                #pragma unroll
                for (int dx = 0; dx < 3; dx++) {
                    int j = px + dx;
                    float m = fmaf(sgv[j], hc[pr + px], hwv[j]);
                    if (m <= 0.f) acc[pr + px] += enc[j];
                }
            }
        };

        load6(y0,     0, encA, sgA, hwA);
        load6(y0 + 1, 4, encB, sgB, hwB);

        // softmax + unified pred + tversky prob partials (flm now complete)
        {
            float t[8] = {l1a.x - l0a.x, l1a.y - l0a.y, l1a.z - l0a.z, l1a.w - l0a.w,
                          l1b.x - l0b.x, l1b.y - l0b.y, l1b.z - l0b.z, l1b.w - l0b.w};
            #pragma unroll
            for (int p = 0; p < 8; p++) {
                float p1 = 1.0f / (1.0f + __expf(-t[p]));
                s_p1 += p1;
                if ((flm >> p) & 1u) s_i1 += p1;
                u[p] = (t[p] > 0.f) ? p1 : p1 - 1.f;
            }
        }

        sten(0, encA, sgA, hwA);      // row y0   -> pixel row 0
        sten(4, encA, sgA, hwA);      // row y0   -> pixel row 1
        sten(0, encB, sgB, hwB);      // row y0+1 -> pixel row 0
        sten(4, encB, sgB, hwB);      // row y0+1 -> pixel row 1

        load6(y0 - 1, -1, encA, sgA, hwA);
        sten(0, encA, sgA, hwA);      // row y0-1 -> pixel row 0
        load6(y0 + 2, -1, encA, sgA, hwA);
        sten(4, encA, sgA, hwA);      // row y0+2 -> pixel row 1

        #pragma unroll
        for (int p = 0; p < 8; p++) {
            int cb = acc[p] >> 16;
            int dd = (acc[p] & 0xFFFF) - cb;
            cbi += cb;
            s_ud = fmaf(u[p], (float)dd, s_ud);
        }
    }

    // ---- per-block reduction ----
    __shared__ float sh[NT / 32];
    {
        float acc[NACC] = {s_p1, s_i1, (float)__popc(flm), (float)cbi, s_ud};
        #pragma unroll
        for (int k = 0; k < NACC; k++) {
            float r = block_reduce(acc[k], sh);
            if (threadIdx.x == 0) g_part[blockIdx.x * 8 + k] = r;
        }
    }

    // ---- last-block finalize ----
    __shared__ bool is_last;
    if (threadIdx.x == 0) {
        __threadfence();                     // publish this block's partials
        unsigned c = atomicAdd(&g_count, 1u);
        is_last = (c == (unsigned)(NB - 1));
    }
    __syncthreads();
    if (!is_last) return;
    __threadfence();                         // acquire all blocks' partials

    float acc[NACC];
    #pragma unroll
    for (int k = 0; k < NACC; k++) acc[k] = 0.0f;
    for (int i = threadIdx.x; i < NB; i += NT) {
        #pragma unroll
        for (int k = 0; k < NACC; k++) acc[k] += g_part[i * 8 + k];
    }
    float tot[NACC];
    #pragma unroll
    for (int k = 0; k < NACC; k++) tot[k] = block_reduce(acc[k], sh);

    if (threadIdx.x == 0) {
        const float ALPHA = 0.3f, BETA = 0.7f, GAMMA = 1.33f, EPS = 1e-7f;
        float p1s  = tot[0];
        float i1   = tot[1];
        float c1   = tot[2];
        float csum = tot[3];
        float uds  = tot[4];

        float p0s = (float)NPIX - p1s;
        float c0  = (float)NPIX - c1;
        float i0  = (float)NPIX - c1 - p1s + i1;   // sum((1-cf)*(1-p1))

        float fp0 = p0s - i0;
        float fn0 = c0 - i0;
        float d0  = fmaxf(i0 + ALPHA * fp0 + BETA * fn0 + EPS, EPS);
        float loss0 = powf(1.0f - i0 / d0, GAMMA) * (c0 > 0.0f ? 1.0f : 0.0f);

        float fp1 = p1s - i1;
        float fn1 = c1 - i1;
        float d1  = fmaxf(i1 + ALPHA * fp1 + BETA * fn1 + EPS, EPS);
        float loss1 = powf(1.0f - i1 / d1, GAMMA) * (c1 > 0.0f ? 1.0f : 0.0f);

        float tversky = 0.5f * (loss0 + loss1);
        float elev    = (csum + uds) / fmaxf(csum, 1.0f);

        out[0] = tversky * elev;
        g_count = 0;   // reset for next graph replay
    }
}

extern "C" void kernel_launch(void* const* d_in, const int* in_sizes, int n_in,
                              void* d_out, int out_size)
{
    const float* pred = (const float*)d_in[0];   // (8,2,512,512) f32
    const float* hgt  = (const float*)d_in[1];   // (8,1,512,512) f32
    const int*   gt   = (const int*)  d_in[2];   // (8,1,512,512) i32
    float* out = (float*)d_out;

    elev_fused<<<NB, NT>>>(pred, hgt, gt, out);
}